// round 3
// baseline (speedup 1.0000x reference)
#include <cuda_runtime.h>

#define NN 100000
#define NE 3200000
#define DF 512
#define HID 16
#define NC  40
#define SCAN_CHUNK 1024
#define NB ((NN + SCAN_CHUNK - 1) / SCAN_CHUNK)   // 98

#define GEMM_BLOCKS 782          // ceil(100000/128)
#define GA 391                   // gemm blocks fused into pass1 kernel (rows 0..50047)
#define GB (GEMM_BLOCKS - GA)    // gemm blocks fused into build kernel
#define PB 1089                  // pass1 worker blocks
#define BB 1089                  // build worker blocks

// ---------------- device scratch ----------------
__device__ float g_dinv[NN];
__device__ int   g_cnt[NN];
__device__ int   g_ptr[NN];
__device__ int   g_cur[NN];
__device__ int2  g_edge[NE];
__device__ float g_hx [NN * HID];
__device__ float g_h1 [NN * HID];
__device__ int   g_part[NB];

#define FMA2(d, a, b) asm("fma.rn.f32x2 %0, %1, %2, %0;" : "+l"(d) : "l"(a), "l"(b))

// ---------------- shared GEMM block body: 128 rows of x @ W1 ----------------
__device__ __forceinline__ void gemm_block(const float* __restrict__ x,
                                           const float* __restrict__ W1,
                                           int n, int blk) {
    __shared__ unsigned long long Ws[DF * HID / 2];  // 32 KB
    __shared__ float xs[128][17];                    // 8.5 KB
    int t = threadIdx.x;
    int row = blk * 128 + t;

    const unsigned long long* Wg = (const unsigned long long*)W1;
    for (int i = t; i < DF * HID / 2; i += 128) Ws[i] = Wg[i];

    unsigned long long acc[8];
    #pragma unroll
    for (int p = 0; p < 8; p++) acc[p] = 0ULL;

    for (int jb = 0; jb < DF; jb += 16) {
        __syncthreads();
        #pragma unroll
        for (int i = 0; i < 4; i++) {
            int idx = i * 128 + t;
            int r = idx >> 2, c4 = idx & 3;
            int gr = blk * 128 + r;
            float4 v = (gr < n) ? ((const float4*)&x[gr * DF + jb])[c4]
                                : make_float4(0.f, 0.f, 0.f, 0.f);
            xs[r][c4 * 4 + 0] = v.x;
            xs[r][c4 * 4 + 1] = v.y;
            xs[r][c4 * 4 + 2] = v.z;
            xs[r][c4 * 4 + 3] = v.w;
        }
        __syncthreads();
        #pragma unroll
        for (int c = 0; c < 16; c++) {
            float xv = xs[t][c];
            unsigned long long xx;
            asm("mov.b64 %0, {%1, %1};" : "=l"(xx) : "f"(xv));
            const ulonglong2* wp = (const ulonglong2*)&Ws[(jb + c) * 8];
            ulonglong2 w01 = wp[0], w23 = wp[1];
            FMA2(acc[0], xx, w01.x);
            FMA2(acc[1], xx, w01.y);
            FMA2(acc[2], xx, w23.x);
            FMA2(acc[3], xx, w23.y);
            ulonglong2 w45 = wp[2], w67 = wp[3];
            FMA2(acc[4], xx, w45.x);
            FMA2(acc[5], xx, w45.y);
            FMA2(acc[6], xx, w67.x);
            FMA2(acc[7], xx, w67.y);
        }
    }
    if (row < n) {
        ulonglong2* o = (ulonglong2*)&g_hx[row * HID];
        o[0] = make_ulonglong2(acc[0], acc[1]);
        o[1] = make_ulonglong2(acc[2], acc[3]);
        o[2] = make_ulonglong2(acc[4], acc[5]);
        o[3] = make_ulonglong2(acc[6], acc[7]);
    }
}

// ---------------- init kernels (split so the fused kernel lands at launch idx 3) ----------------
__global__ void k_init_dinv(int n) {
    int i = blockIdx.x * blockDim.x + threadIdx.x;
    if (i < n) g_dinv[i] = 1.0f;
}
__global__ void k_init_cnt(int n) {
    int i = blockIdx.x * blockDim.x + threadIdx.x;
    if (i < n) g_cnt[i] = 0;
}
__global__ void k_init_cur(int n) {
    int i = blockIdx.x * blockDim.x + threadIdx.x;
    if (i < n) g_cur[i] = 0;
}

// ---------------- fused: pass1 (degree+histogram) + gemm half A ----------------
__global__ void __launch_bounds__(128) k_p1_gemmA(const float* __restrict__ x,
                                                  const float* __restrict__ W1,
                                                  const int* __restrict__ col,
                                                  const float* __restrict__ w,
                                                  int E, int n) {
    if (blockIdx.x < GA) {
        gemm_block(x, W1, n, (int)blockIdx.x);
        return;
    }
    int b = blockIdx.x - GA;
    long i0 = ((long)b * 128 + threadIdx.x) * 4;
    long stride = (long)PB * 128 * 4;
    for (long e = i0; e < E; e += stride) {
        if (e + 3 < E) {
            int4   c4 = *(const int4*)  (col + e);
            float4 w4 = *(const float4*)(w   + e);
            atomicAdd(&g_dinv[c4.x], w4.x); atomicAdd(&g_cnt[c4.x], 1);
            atomicAdd(&g_dinv[c4.y], w4.y); atomicAdd(&g_cnt[c4.y], 1);
            atomicAdd(&g_dinv[c4.z], w4.z); atomicAdd(&g_cnt[c4.z], 1);
            atomicAdd(&g_dinv[c4.w], w4.w); atomicAdd(&g_cnt[c4.w], 1);
        } else {
            for (long k = e; k < E; k++) {
                int c = col[k];
                atomicAdd(&g_dinv[c], w[k]);
                atomicAdd(&g_cnt[c], 1);
            }
        }
    }
}

// ---------------- scan A (block sums) + fused rsqrt ----------------
__global__ void k_scanA(int n) {
    __shared__ int sh[256];
    int t = threadIdx.x;
    int base = blockIdx.x * SCAN_CHUNK;
    int s = 0;
    #pragma unroll
    for (int k = 0; k < 4; k++) {
        int idx = base + t + k * 256;
        if (idx < n) {
            s += g_cnt[idx];
            g_dinv[idx] = rsqrtf(g_dinv[idx]);
        }
    }
    sh[t] = s;
    __syncthreads();
    for (int off = 128; off > 0; off >>= 1) {
        if (t < off) sh[t] += sh[t + off];
        __syncthreads();
    }
    if (t == 0) g_part[blockIdx.x] = sh[0];
}

__global__ void k_scanB() {
    __shared__ int s[128];
    int t = threadIdx.x;
    int v = (t < NB) ? g_part[t] : 0;
    s[t] = v;
    __syncthreads();
    #pragma unroll
    for (int off = 1; off < 128; off <<= 1) {
        int a = (t >= off) ? s[t - off] : 0;
        __syncthreads();
        s[t] += a;
        __syncthreads();
    }
    if (t < NB) g_part[t] = s[t] - v;
}

__global__ void k_scanC(int n) {
    __shared__ int s[SCAN_CHUNK];
    int t = threadIdx.x;
    int idx = blockIdx.x * SCAN_CHUNK + t;
    int v = (idx < n) ? g_cnt[idx] : 0;
    s[t] = v;
    __syncthreads();
    for (int off = 1; off < SCAN_CHUNK; off <<= 1) {
        int a = (t >= off) ? s[t - off] : 0;
        __syncthreads();
        s[t] += a;
        __syncthreads();
    }
    if (idx < n) g_ptr[idx] = g_part[blockIdx.x] + s[t] - v;
}

// ---------------- fused: CSR build scatter + gemm half B ----------------
__global__ void __launch_bounds__(128) k_build_gemmB(const float* __restrict__ x,
                                                     const float* __restrict__ W1,
                                                     const int* __restrict__ row,
                                                     const int* __restrict__ col,
                                                     const float* __restrict__ w,
                                                     int E, int n) {
    if (blockIdx.x < GB) {
        gemm_block(x, W1, n, GA + (int)blockIdx.x);
        return;
    }
    int b = blockIdx.x - GB;
    long i0 = ((long)b * 128 + threadIdx.x) * 4;
    long stride = (long)BB * 128 * 4;
    for (long e = i0; e < E; e += stride) {
        if (e + 3 < E) {
            int4   r4 = *(const int4*)  (row + e);
            int4   c4 = *(const int4*)  (col + e);
            float4 w4 = *(const float4*)(w   + e);
            {
                float nv = g_dinv[r4.x] * w4.x * g_dinv[c4.x];
                int pos = g_ptr[c4.x] + atomicAdd(&g_cur[c4.x], 1);
                g_edge[pos] = make_int2(r4.x, __float_as_int(nv));
            }
            {
                float nv = g_dinv[r4.y] * w4.y * g_dinv[c4.y];
                int pos = g_ptr[c4.y] + atomicAdd(&g_cur[c4.y], 1);
                g_edge[pos] = make_int2(r4.y, __float_as_int(nv));
            }
            {
                float nv = g_dinv[r4.z] * w4.z * g_dinv[c4.z];
                int pos = g_ptr[c4.z] + atomicAdd(&g_cur[c4.z], 1);
                g_edge[pos] = make_int2(r4.z, __float_as_int(nv));
            }
            {
                float nv = g_dinv[r4.w] * w4.w * g_dinv[c4.w];
                int pos = g_ptr[c4.w] + atomicAdd(&g_cur[c4.w], 1);
                g_edge[pos] = make_int2(r4.w, __float_as_int(nv));
            }
        } else {
            for (long k = e; k < E; k++) {
                int r = row[k], c = col[k];
                float nv = g_dinv[r] * w[k] * g_dinv[c];
                int pos = g_ptr[c] + atomicAdd(&g_cur[c], 1);
                g_edge[pos] = make_int2(r, __float_as_int(nv));
            }
        }
    }
}

// ---------------- agg phase 1: g_h1 = relu(A_hat @ g_hx + b1) ----------------
__global__ void k_agg1(const float* __restrict__ bias, int n) {
    const float4* in = (const float4*)g_hx;
    int node = (blockIdx.x * blockDim.x + threadIdx.x) >> 5;
    int lane = threadIdx.x & 31;
    if (node >= n) return;

    int q  = lane & 3;
    int es = lane >> 2;
    int start = g_ptr[node];
    int end   = start + g_cnt[node];

    float4 acc = make_float4(0.f, 0.f, 0.f, 0.f);
    for (int e = start + es; e < end; e += 8) {
        int2  ev  = __ldg(&g_edge[e]);
        float nv  = __int_as_float(ev.y);
        float4 v  = in[ev.x * 4 + q];
        acc.x += nv * v.x; acc.y += nv * v.y; acc.z += nv * v.z; acc.w += nv * v.w;
    }
    #pragma unroll
    for (int off = 4; off < 32; off <<= 1) {
        acc.x += __shfl_down_sync(0xffffffffu, acc.x, off);
        acc.y += __shfl_down_sync(0xffffffffu, acc.y, off);
        acc.z += __shfl_down_sync(0xffffffffu, acc.z, off);
        acc.w += __shfl_down_sync(0xffffffffu, acc.w, off);
    }
    if (lane < 4) {
        float d  = g_dinv[node];
        float d2 = d * d;
        float4 sv = in[node * 4 + lane];
        acc.x += d2 * sv.x; acc.y += d2 * sv.y; acc.z += d2 * sv.z; acc.w += d2 * sv.w;
        float4 b = ((const float4*)bias)[lane];
        acc.x = fmaxf(acc.x + b.x, 0.f);
        acc.y = fmaxf(acc.y + b.y, 0.f);
        acc.z = fmaxf(acc.z + b.z, 0.f);
        acc.w = fmaxf(acc.w + b.w, 0.f);
        ((float4*)g_h1)[node * 4 + lane] = acc;
    }
}

// ---------------- agg phase 2 fused with output GEMM ----------------
__global__ void k_agg2_out(float* __restrict__ out, const float* __restrict__ W2,
                           const float* __restrict__ b2, int n) {
    __shared__ float W2s[HID * NC];
    __shared__ float b2s[NC];
    int tid = threadIdx.x;
    for (int i = tid; i < HID * NC; i += blockDim.x) W2s[i] = W2[i];
    if (tid < NC) b2s[tid] = b2[tid];
    __syncthreads();

    const float4* in = (const float4*)g_h1;
    int node = (blockIdx.x * blockDim.x + tid) >> 5;
    int lane = tid & 31;
    if (node >= n) return;

    int q  = lane & 3;
    int es = lane >> 2;
    int start = g_ptr[node];
    int end   = start + g_cnt[node];

    float4 acc = make_float4(0.f, 0.f, 0.f, 0.f);
    for (int e = start + es; e < end; e += 8) {
        int2  ev  = __ldg(&g_edge[e]);
        float nv  = __int_as_float(ev.y);
        float4 v  = in[ev.x * 4 + q];
        acc.x += nv * v.x; acc.y += nv * v.y; acc.z += nv * v.z; acc.w += nv * v.w;
    }
    #pragma unroll
    for (int off = 4; off < 32; off <<= 1) {
        acc.x += __shfl_down_sync(0xffffffffu, acc.x, off);
        acc.y += __shfl_down_sync(0xffffffffu, acc.y, off);
        acc.z += __shfl_down_sync(0xffffffffu, acc.z, off);
        acc.w += __shfl_down_sync(0xffffffffu, acc.w, off);
    }
    if (lane < 4) {
        float d  = g_dinv[node];
        float d2 = d * d;
        float4 sv = in[node * 4 + lane];
        acc.x += d2 * sv.x; acc.y += d2 * sv.y; acc.z += d2 * sv.z; acc.w += d2 * sv.w;
    }
    float h[16];
    #pragma unroll
    for (int s = 0; s < 4; s++) {
        h[4 * s + 0] = __shfl_sync(0xffffffffu, acc.x, s);
        h[4 * s + 1] = __shfl_sync(0xffffffffu, acc.y, s);
        h[4 * s + 2] = __shfl_sync(0xffffffffu, acc.z, s);
        h[4 * s + 3] = __shfl_sync(0xffffffffu, acc.w, s);
    }
    if (lane < NC / 2) {
        int c = 2 * lane;
        float s0 = b2s[c], s1 = b2s[c + 1];
        #pragma unroll
        for (int k = 0; k < HID; k++) {
            s0 += h[k] * W2s[k * NC + c];
            s1 += h[k] * W2s[k * NC + c + 1];
        }
        ((float2*)&out[node * NC])[lane] = make_float2(s0, s1);
    }
}

// ---------------- launch ----------------
extern "C" void kernel_launch(void* const* d_in, const int* in_sizes, int n_in,
                              void* d_out, int out_size) {
    const float* x  = (const float*)d_in[0];
    const int*   ei = (const int*)  d_in[1];
    const float* ew = (const float*)d_in[2];
    const float* W1 = (const float*)d_in[3];
    const float* b1 = (const float*)d_in[4];
    const float* W2 = (const float*)d_in[5];
    const float* b2 = (const float*)d_in[6];

    int E = in_sizes[2];
    int n = in_sizes[0] / DF;
    const int* rowp = ei;
    const int* colp = ei + E;

    int nb256 = (n + 255) / 256;

    k_init_dinv<<<nb256, 256>>>(n);                            // 0
    k_init_cnt <<<nb256, 256>>>(n);                            // 1
    k_init_cur <<<nb256, 256>>>(n);                            // 2
    k_p1_gemmA <<<GA + PB, 128>>>(x, W1, colp, ew, E, n);      // 3  <- profiled
    k_scanA    <<<NB, 256>>>(n);                               // 4
    k_scanB    <<<1, 128>>>();                                 // 5
    k_scanC    <<<NB, SCAN_CHUNK>>>(n);                        // 6
    k_build_gemmB<<<GB + BB, 128>>>(x, W1, rowp, colp, ew, E, n); // 7
    long wthreads = (long)n * 32;
    int aggblocks = (int)((wthreads + 255) / 256);
    k_agg1     <<<aggblocks, 256>>>(b1, n);                    // 8
    k_agg2_out <<<aggblocks, 256>>>((float*)d_out, W2, b2, n); // 9
}

// round 4
// speedup vs baseline: 1.3305x; 1.3305x over previous
#include <cuda_runtime.h>

#define NN 100000
#define NE 3200000
#define DF 512
#define HID 16
#define NC  40
#define SCAN_CHUNK 1024
#define NB ((NN + SCAN_CHUNK - 1) / SCAN_CHUNK)   // 98

// ---------------- device scratch ----------------
__device__ unsigned long long g_pack[NN];  // (cnt << 40) | fixed20(weighted degree)
__device__ float g_dinv[NN];               // d^-1/2
__device__ int   g_cnt[NN];                // in-degree (edges only)
__device__ int   g_ptr[NN];                // CSR offsets; after build: end offsets
__device__ int2  g_edge[NE];               // (src, w-as-int) per CSR slot
__device__ float g_hx [NN * HID];          // dinv[row] * (x @ W1)
__device__ float g_h1 [NN * HID];          // dinv[dst] * relu(...)
__device__ int   g_part[NB];

#define FMA2(d, a, b) asm("fma.rn.f32x2 %0, %1, %2, %0;" : "+l"(d) : "l"(a), "l"(b))
#define MUL2(d, a, b) asm("mul.rn.f32x2 %0, %1, %2;" : "=l"(d) : "l"(a), "l"(b))

// ---------------- 0: init (self-loop weight 1.0 -> fixed 2^20, count 0) ----------------
__global__ void k_init(int n) {
    int i = blockIdx.x * blockDim.x + threadIdx.x;
    if (i < n) g_pack[i] = (1ULL << 20);
}

// ---------------- 1: pass1 — single packed 64-bit atomic per edge ----------------
__global__ void __launch_bounds__(256) k_pass1(const int* __restrict__ col,
                                               const float* __restrict__ w, int E) {
    long i0 = ((long)blockIdx.x * blockDim.x + threadIdx.x) * 4;
    if (i0 >= E) return;
    if (i0 + 3 < E) {
        int4   c4 = *(const int4*)  (col + i0);
        float4 w4 = *(const float4*)(w   + i0);
        atomicAdd(&g_pack[c4.x], (1ULL << 40) + (unsigned long long)(w4.x * 1048576.0f + 0.5f));
        atomicAdd(&g_pack[c4.y], (1ULL << 40) + (unsigned long long)(w4.y * 1048576.0f + 0.5f));
        atomicAdd(&g_pack[c4.z], (1ULL << 40) + (unsigned long long)(w4.z * 1048576.0f + 0.5f));
        atomicAdd(&g_pack[c4.w], (1ULL << 40) + (unsigned long long)(w4.w * 1048576.0f + 0.5f));
    } else {
        for (long k = i0; k < E; k++)
            atomicAdd(&g_pack[col[k]], (1ULL << 40) + (unsigned long long)(w[k] * 1048576.0f + 0.5f));
    }
}

// ---------------- 2: scanA — unpack, rsqrt, per-chunk sums ----------------
__global__ void k_scanA(int n) {
    __shared__ int sh[256];
    int t = threadIdx.x;
    int base = blockIdx.x * SCAN_CHUNK;
    int s = 0;
    #pragma unroll
    for (int k = 0; k < 4; k++) {
        int idx = base + t + k * 256;
        if (idx < n) {
            unsigned long long p = g_pack[idx];
            int cnt = (int)(p >> 40);
            float deg = (float)(p & ((1ULL << 40) - 1)) * (1.0f / 1048576.0f);
            g_cnt[idx]  = cnt;
            g_dinv[idx] = rsqrtf(deg);      // deg >= 1 (self loop)
            s += cnt;
        }
    }
    sh[t] = s;
    __syncthreads();
    for (int off = 128; off > 0; off >>= 1) {
        if (t < off) sh[t] += sh[t + off];
        __syncthreads();
    }
    if (t == 0) g_part[blockIdx.x] = sh[0];
}

// ---------------- 3: GEMM1 (PROFILED) — g_hx = dinv[row] * (x @ W1) ----------------
__global__ void __launch_bounds__(128) k_gemm1(const float* __restrict__ x,
                                               const float* __restrict__ W1, int n) {
    __shared__ unsigned long long Ws[DF * HID / 2];  // 32 KB
    __shared__ float xs[128][17];
    int t = threadIdx.x;
    int row = blockIdx.x * 128 + t;

    const unsigned long long* Wg = (const unsigned long long*)W1;
    for (int i = t; i < DF * HID / 2; i += 128) Ws[i] = Wg[i];

    unsigned long long acc[8];
    #pragma unroll
    for (int p = 0; p < 8; p++) acc[p] = 0ULL;

    for (int jb = 0; jb < DF; jb += 16) {
        __syncthreads();
        #pragma unroll
        for (int i = 0; i < 4; i++) {
            int idx = i * 128 + t;
            int r = idx >> 2, c4 = idx & 3;
            int gr = blockIdx.x * 128 + r;
            float4 v = (gr < n) ? ((const float4*)&x[gr * DF + jb])[c4]
                                : make_float4(0.f, 0.f, 0.f, 0.f);
            xs[r][c4 * 4 + 0] = v.x;
            xs[r][c4 * 4 + 1] = v.y;
            xs[r][c4 * 4 + 2] = v.z;
            xs[r][c4 * 4 + 3] = v.w;
        }
        __syncthreads();
        #pragma unroll
        for (int c = 0; c < 16; c++) {
            float xv = xs[t][c];
            unsigned long long xx;
            asm("mov.b64 %0, {%1, %1};" : "=l"(xx) : "f"(xv));
            const ulonglong2* wp = (const ulonglong2*)&Ws[(jb + c) * 8];
            ulonglong2 w01 = wp[0], w23 = wp[1];
            FMA2(acc[0], xx, w01.x);
            FMA2(acc[1], xx, w01.y);
            FMA2(acc[2], xx, w23.x);
            FMA2(acc[3], xx, w23.y);
            ulonglong2 w45 = wp[2], w67 = wp[3];
            FMA2(acc[4], xx, w45.x);
            FMA2(acc[5], xx, w45.y);
            FMA2(acc[6], xx, w67.x);
            FMA2(acc[7], xx, w67.y);
        }
    }
    if (row < n) {
        float d = g_dinv[row];
        unsigned long long dd;
        asm("mov.b64 %0, {%1, %1};" : "=l"(dd) : "f"(d));
        #pragma unroll
        for (int p = 0; p < 8; p++) MUL2(acc[p], acc[p], dd);
        ulonglong2* o = (ulonglong2*)&g_hx[row * HID];
        o[0] = make_ulonglong2(acc[0], acc[1]);
        o[1] = make_ulonglong2(acc[2], acc[3]);
        o[2] = make_ulonglong2(acc[4], acc[5]);
        o[3] = make_ulonglong2(acc[6], acc[7]);
    }
}

// ---------------- 4: scanC — local scan of partials + chunk scan -> g_ptr ----------------
__global__ void k_scanC(int n) {
    __shared__ int sp[128];
    __shared__ int s[SCAN_CHUNK];
    int t = threadIdx.x % 128;
    int tid = threadIdx.x;

    // local inclusive scan of the 98 block partials (first 128 threads)
    if (tid < 128) {
        int v = (tid < NB) ? g_part[tid] : 0;
        sp[tid] = v;
    }
    __syncthreads();
    if (tid < 128) {
        #pragma unroll
        for (int off = 1; off < 128; off <<= 1) {
            int a = (t >= off) ? sp[t - off] : 0;
            __syncthreads();
            sp[t] += a;
            __syncthreads();
        }
    } else {
        #pragma unroll
        for (int off = 1; off < 128; off <<= 1) { __syncthreads(); __syncthreads(); }
    }
    __syncthreads();
    int blockOff = (blockIdx.x > 0) ? sp[blockIdx.x - 1] : 0;

    int idx = blockIdx.x * SCAN_CHUNK + tid;
    int v = (idx < n) ? g_cnt[idx] : 0;
    s[tid] = v;
    __syncthreads();
    for (int off = 1; off < SCAN_CHUNK; off <<= 1) {
        int a = (tid >= off) ? s[tid - off] : 0;
        __syncthreads();
        s[tid] += a;
        __syncthreads();
    }
    if (idx < n) g_ptr[idx] = blockOff + s[tid] - v;   // exclusive prefix
}

// ---------------- 5: build — scatter (src, w); cursor folded into g_ptr ----------------
__global__ void __launch_bounds__(256) k_build(const int* __restrict__ row,
                                               const int* __restrict__ col,
                                               const float* __restrict__ w, int E) {
    long i0 = ((long)blockIdx.x * blockDim.x + threadIdx.x) * 4;
    if (i0 >= E) return;
    if (i0 + 3 < E) {
        int4   r4 = *(const int4*)  (row + i0);
        int4   c4 = *(const int4*)  (col + i0);
        float4 w4 = *(const float4*)(w   + i0);
        int p0 = atomicAdd(&g_ptr[c4.x], 1);
        g_edge[p0] = make_int2(r4.x, __float_as_int(w4.x));
        int p1 = atomicAdd(&g_ptr[c4.y], 1);
        g_edge[p1] = make_int2(r4.y, __float_as_int(w4.y));
        int p2 = atomicAdd(&g_ptr[c4.z], 1);
        g_edge[p2] = make_int2(r4.z, __float_as_int(w4.z));
        int p3 = atomicAdd(&g_ptr[c4.w], 1);
        g_edge[p3] = make_int2(r4.w, __float_as_int(w4.w));
    } else {
        for (long k = i0; k < E; k++) {
            int pos = atomicAdd(&g_ptr[col[k]], 1);
            g_edge[pos] = make_int2(row[k], __float_as_int(w[k]));
        }
    }
}

// ---------------- 6: agg1 — g_h1 = dinv_d * relu(dinv_d*(Σ w·hx_s + hx_s[self]) + b1) ----------------
__global__ void k_agg1(const float* __restrict__ bias, int n) {
    const float4* in = (const float4*)g_hx;
    int node = (blockIdx.x * blockDim.x + threadIdx.x) >> 5;
    int lane = threadIdx.x & 31;
    if (node >= n) return;

    int q  = lane & 3;
    int es = lane >> 2;
    int end   = g_ptr[node];           // post-build: end offset
    int start = end - g_cnt[node];

    float4 acc = make_float4(0.f, 0.f, 0.f, 0.f);
    for (int e = start + es; e < end; e += 8) {
        int2  ev = __ldg(&g_edge[e]);
        float wv = __int_as_float(ev.y);
        float4 v = in[ev.x * 4 + q];
        acc.x += wv * v.x; acc.y += wv * v.y; acc.z += wv * v.z; acc.w += wv * v.w;
    }
    #pragma unroll
    for (int off = 4; off < 32; off <<= 1) {
        acc.x += __shfl_down_sync(0xffffffffu, acc.x, off);
        acc.y += __shfl_down_sync(0xffffffffu, acc.y, off);
        acc.z += __shfl_down_sync(0xffffffffu, acc.z, off);
        acc.w += __shfl_down_sync(0xffffffffu, acc.w, off);
    }
    if (lane < 4) {
        float d = g_dinv[node];
        float4 sv = in[node * 4 + lane];
        float4 b = ((const float4*)bias)[lane];
        acc.x = d * fmaxf(d * (acc.x + sv.x) + b.x, 0.f);
        acc.y = d * fmaxf(d * (acc.y + sv.y) + b.y, 0.f);
        acc.z = d * fmaxf(d * (acc.z + sv.z) + b.z, 0.f);
        acc.w = d * fmaxf(d * (acc.w + sv.w) + b.w, 0.f);
        ((float4*)g_h1)[node * 4 + lane] = acc;
    }
}

// ---------------- 7: agg2 + output GEMM ----------------
__global__ void k_agg2_out(float* __restrict__ out, const float* __restrict__ W2,
                           const float* __restrict__ b2, int n) {
    __shared__ float W2s[HID * NC];
    __shared__ float b2s[NC];
    int tid = threadIdx.x;
    for (int i = tid; i < HID * NC; i += blockDim.x) W2s[i] = W2[i];
    if (tid < NC) b2s[tid] = b2[tid];
    __syncthreads();

    const float4* in = (const float4*)g_h1;
    int node = (blockIdx.x * blockDim.x + tid) >> 5;
    int lane = tid & 31;
    if (node >= n) return;

    int q  = lane & 3;
    int es = lane >> 2;
    int end   = g_ptr[node];
    int start = end - g_cnt[node];

    float4 acc = make_float4(0.f, 0.f, 0.f, 0.f);
    for (int e = start + es; e < end; e += 8) {
        int2  ev = __ldg(&g_edge[e]);
        float wv = __int_as_float(ev.y);
        float4 v = in[ev.x * 4 + q];
        acc.x += wv * v.x; acc.y += wv * v.y; acc.z += wv * v.z; acc.w += wv * v.w;
    }
    #pragma unroll
    for (int off = 4; off < 32; off <<= 1) {
        acc.x += __shfl_down_sync(0xffffffffu, acc.x, off);
        acc.y += __shfl_down_sync(0xffffffffu, acc.y, off);
        acc.z += __shfl_down_sync(0xffffffffu, acc.z, off);
        acc.w += __shfl_down_sync(0xffffffffu, acc.w, off);
    }
    if (lane < 4) {
        float d = g_dinv[node];
        float4 sv = in[node * 4 + lane];
        acc.x = d * (acc.x + sv.x);
        acc.y = d * (acc.y + sv.y);
        acc.z = d * (acc.z + sv.z);
        acc.w = d * (acc.w + sv.w);
    }
    float h[16];
    #pragma unroll
    for (int s = 0; s < 4; s++) {
        h[4 * s + 0] = __shfl_sync(0xffffffffu, acc.x, s);
        h[4 * s + 1] = __shfl_sync(0xffffffffu, acc.y, s);
        h[4 * s + 2] = __shfl_sync(0xffffffffu, acc.z, s);
        h[4 * s + 3] = __shfl_sync(0xffffffffu, acc.w, s);
    }
    if (lane < NC / 2) {
        int c = 2 * lane;
        float s0 = b2s[c], s1 = b2s[c + 1];
        #pragma unroll
        for (int k = 0; k < HID; k++) {
            s0 += h[k] * W2s[k * NC + c];
            s1 += h[k] * W2s[k * NC + c + 1];
        }
        ((float2*)&out[node * NC])[lane] = make_float2(s0, s1);
    }
}

// ---------------- launch ----------------
extern "C" void kernel_launch(void* const* d_in, const int* in_sizes, int n_in,
                              void* d_out, int out_size) {
    const float* x  = (const float*)d_in[0];
    const int*   ei = (const int*)  d_in[1];
    const float* ew = (const float*)d_in[2];
    const float* W1 = (const float*)d_in[3];
    const float* b1 = (const float*)d_in[4];
    const float* W2 = (const float*)d_in[5];
    const float* b2 = (const float*)d_in[6];

    int E = in_sizes[2];
    int n = in_sizes[0] / DF;
    const int* rowp = ei;
    const int* colp = ei + E;

    int nb256 = (n + 255) / 256;
    int eb4   = (int)(((long)E + 1023) / 1024);   // 256 threads x 4 edges

    k_init  <<<nb256, 256>>>(n);                          // 0
    k_pass1 <<<eb4, 256>>>(colp, ew, E);                  // 1
    k_scanA <<<NB, 256>>>(n);                             // 2
    k_gemm1 <<<(n + 127) / 128, 128>>>(x, W1, n);         // 3  <- profiled
    k_scanC <<<NB, SCAN_CHUNK>>>(n);                      // 4
    k_build <<<eb4, 256>>>(rowp, colp, ew, E);            // 5
    long wthreads = (long)n * 32;
    int aggblocks = (int)((wthreads + 255) / 256);
    k_agg1     <<<aggblocks, 256>>>(b1, n);               // 6
    k_agg2_out <<<aggblocks, 256>>>((float*)d_out, W2, b2, n); // 7
}

// round 6
// speedup vs baseline: 1.4119x; 1.0612x over previous
#include <cuda_runtime.h>

#define NN 100000
#define NE 3200000
#define DF 512
#define HID 16
#define NC  40
#define SCAN_CHUNK 1024
#define NB ((NN + SCAN_CHUNK - 1) / SCAN_CHUNK)   // 98

typedef unsigned long long ull;

// ---------------- device scratch ----------------
__device__ ull   g_pack[NN];   // (cnt << 40) | fixed20(weighted degree)
__device__ float g_dinv[NN];   // d^-1/2
__device__ int   g_cnt[NN];    // in-degree (edges only)
__device__ int   g_ptr[NN];    // CSR offsets; after build: end offsets
__device__ int2  g_edge[NE];   // (src, w-as-int) per CSR slot
__device__ float g_hx [NN * HID];
__device__ float g_h1 [NN * HID];
__device__ int   g_part[NB];

#define FMA2(d, a, b) asm("fma.rn.f32x2 %0, %1, %2, %0;" : "+l"(d) : "l"(a), "l"(b))
#define MUL2(d, a, b) asm("mul.rn.f32x2 %0, %1, %2;" : "=l"(d) : "l"(a), "l"(b))

// ---------------- 0: init ----------------
__global__ void k_init(int n) {
    int i = blockIdx.x * blockDim.x + threadIdx.x;
    if (i < n) g_pack[i] = (1ULL << 20);   // self-loop w=1.0 in fixed20, cnt=0
}

// ---------------- 1: pass1 — single packed 64-bit atomic per edge ----------------
__global__ void __launch_bounds__(256) k_pass1(const int* __restrict__ col,
                                               const float* __restrict__ w, int E) {
    long i0 = ((long)blockIdx.x * blockDim.x + threadIdx.x) * 4;
    if (i0 >= E) return;
    if (i0 + 3 < E) {
        int4   c4 = *(const int4*)  (col + i0);
        float4 w4 = *(const float4*)(w   + i0);
        atomicAdd(&g_pack[c4.x], (1ULL << 40) + (ull)(w4.x * 1048576.0f + 0.5f));
        atomicAdd(&g_pack[c4.y], (1ULL << 40) + (ull)(w4.y * 1048576.0f + 0.5f));
        atomicAdd(&g_pack[c4.z], (1ULL << 40) + (ull)(w4.z * 1048576.0f + 0.5f));
        atomicAdd(&g_pack[c4.w], (1ULL << 40) + (ull)(w4.w * 1048576.0f + 0.5f));
    } else {
        for (long k = i0; k < E; k++)
            atomicAdd(&g_pack[col[k]], (1ULL << 40) + (ull)(w[k] * 1048576.0f + 0.5f));
    }
}

// ---------------- 2: scanA — unpack, rsqrt, per-chunk sums ----------------
__global__ void k_scanA(int n) {
    __shared__ int sh[256];
    int t = threadIdx.x;
    int base = blockIdx.x * SCAN_CHUNK;
    int s = 0;
    #pragma unroll
    for (int k = 0; k < 4; k++) {
        int idx = base + t + k * 256;
        if (idx < n) {
            ull p = g_pack[idx];
            int cnt = (int)(p >> 40);
            float deg = (float)(p & ((1ULL << 40) - 1)) * (1.0f / 1048576.0f);
            g_cnt[idx]  = cnt;
            g_dinv[idx] = rsqrtf(deg);
            s += cnt;
        }
    }
    sh[t] = s;
    __syncthreads();
    for (int off = 128; off > 0; off >>= 1) {
        if (t < off) sh[t] += sh[t + off];
        __syncthreads();
    }
    if (t == 0) g_part[blockIdx.x] = sh[0];
}

// ---------------- 3: GEMM1 (PROFILED) — g_hx = dinv[row] * (x @ W1) ----------------
// 256 threads = 8 autonomous warps; W shared (LDS.128 broadcast), per-warp x slices
// (stride-17, SCALAR access only -> conflict-free AND aligned); no block syncs in loop.
__global__ void __launch_bounds__(256) k_gemm1(const float* __restrict__ x,
                                               const float* __restrict__ W1, int n) {
    __shared__ ull   Ws[DF * HID / 2];    // 32 KB; Ws[k*8+p] = W1[k*16+2p..2p+1]
    __shared__ float xs[8][32][17];       // 17.4 KB, per-warp slices
    int t = threadIdx.x;
    int w = t >> 5, l = t & 31;
    int lr = l >> 2;                      // sub-row 0..7
    int lc = l & 3;                       // col-quad 0..3

    {   // cooperative W load (only block-wide sync in the kernel)
        const ulonglong2* Wg = (const ulonglong2*)W1;
        ulonglong2* Ws2 = (ulonglong2*)Ws;
        #pragma unroll
        for (int i = 0; i < DF * HID / 4 / 256; i++)
            Ws2[i * 256 + t] = Wg[i * 256 + t];
    }
    __syncthreads();

    int rowbase = blockIdx.x * 256 + w * 32;
    int row = rowbase + l;

    ull acc[8];
    #pragma unroll
    for (int p = 0; p < 8; p++) acc[p] = 0ULL;

    // register prefetch of chunk 0: rows rowbase+8i+lr, cols lc*4..lc*4+3
    float4 r0, r1, r2, r3;
    {
        int gr0 = rowbase + 0  + lr, gr1 = rowbase + 8  + lr;
        int gr2 = rowbase + 16 + lr, gr3 = rowbase + 24 + lr;
        const float4 z = make_float4(0.f, 0.f, 0.f, 0.f);
        r0 = (gr0 < n) ? ((const float4*)&x[(size_t)gr0 * DF])[lc] : z;
        r1 = (gr1 < n) ? ((const float4*)&x[(size_t)gr1 * DF])[lc] : z;
        r2 = (gr2 < n) ? ((const float4*)&x[(size_t)gr2 * DF])[lc] : z;
        r3 = (gr3 < n) ? ((const float4*)&x[(size_t)gr3 * DF])[lc] : z;
    }

    for (int jb = 0; jb < DF; jb += 16) {
        __syncwarp();
        // scalar stores: stride-17 rows, bank = (17*row + col) % 32 — conflict-free
        xs[w][lr +  0][lc * 4 + 0] = r0.x; xs[w][lr +  0][lc * 4 + 1] = r0.y;
        xs[w][lr +  0][lc * 4 + 2] = r0.z; xs[w][lr +  0][lc * 4 + 3] = r0.w;
        xs[w][lr +  8][lc * 4 + 0] = r1.x; xs[w][lr +  8][lc * 4 + 1] = r1.y;
        xs[w][lr +  8][lc * 4 + 2] = r1.z; xs[w][lr +  8][lc * 4 + 3] = r1.w;
        xs[w][lr + 16][lc * 4 + 0] = r2.x; xs[w][lr + 16][lc * 4 + 1] = r2.y;
        xs[w][lr + 16][lc * 4 + 2] = r2.z; xs[w][lr + 16][lc * 4 + 3] = r2.w;
        xs[w][lr + 24][lc * 4 + 0] = r3.x; xs[w][lr + 24][lc * 4 + 1] = r3.y;
        xs[w][lr + 24][lc * 4 + 2] = r3.z; xs[w][lr + 24][lc * 4 + 3] = r3.w;
        __syncwarp();

        if (jb + 16 < DF) {   // prefetch next chunk while computing this one
            int j2 = jb + 16;
            int gr0 = rowbase + 0  + lr, gr1 = rowbase + 8  + lr;
            int gr2 = rowbase + 16 + lr, gr3 = rowbase + 24 + lr;
            const float4 z = make_float4(0.f, 0.f, 0.f, 0.f);
            r0 = (gr0 < n) ? ((const float4*)&x[(size_t)gr0 * DF + j2])[lc] : z;
            r1 = (gr1 < n) ? ((const float4*)&x[(size_t)gr1 * DF + j2])[lc] : z;
            r2 = (gr2 < n) ? ((const float4*)&x[(size_t)gr2 * DF + j2])[lc] : z;
            r3 = (gr3 < n) ? ((const float4*)&x[(size_t)gr3 * DF + j2])[lc] : z;
        }

        #pragma unroll
        for (int c = 0; c < 16; c++) {
            float xv = xs[w][l][c];        // scalar LDS, conflict-free
            ull xx;
            asm("mov.b64 %0, {%1, %1};" : "=l"(xx) : "f"(xv));
            const ulonglong2* wp = (const ulonglong2*)&Ws[(jb + c) * 8];
            ulonglong2 w01 = wp[0], w23 = wp[1];
            FMA2(acc[0], xx, w01.x);
            FMA2(acc[1], xx, w01.y);
            FMA2(acc[2], xx, w23.x);
            FMA2(acc[3], xx, w23.y);
            ulonglong2 w45 = wp[2], w67 = wp[3];
            FMA2(acc[4], xx, w45.x);
            FMA2(acc[5], xx, w45.y);
            FMA2(acc[6], xx, w67.x);
            FMA2(acc[7], xx, w67.y);
        }
    }

    if (row < n) {
        float d = g_dinv[row];
        ull dd;
        asm("mov.b64 %0, {%1, %1};" : "=l"(dd) : "f"(d));
        #pragma unroll
        for (int p = 0; p < 8; p++) MUL2(acc[p], acc[p], dd);
        ulonglong2* o = (ulonglong2*)&g_hx[(size_t)row * HID];
        o[0] = make_ulonglong2(acc[0], acc[1]);
        o[1] = make_ulonglong2(acc[2], acc[3]);
        o[2] = make_ulonglong2(acc[4], acc[5]);
        o[3] = make_ulonglong2(acc[6], acc[7]);
    }
}

// ---------------- 4: scanC — local scan of partials + chunk scan -> g_ptr ----------------
__global__ void k_scanC(int n) {
    __shared__ int sp[128];
    __shared__ int s[SCAN_CHUNK];
    int t = threadIdx.x % 128;
    int tid = threadIdx.x;

    if (tid < 128) sp[tid] = (tid < NB) ? g_part[tid] : 0;
    __syncthreads();
    if (tid < 128) {
        #pragma unroll
        for (int off = 1; off < 128; off <<= 1) {
            int a = (t >= off) ? sp[t - off] : 0;
            __syncthreads();
            sp[t] += a;
            __syncthreads();
        }
    } else {
        #pragma unroll
        for (int off = 1; off < 128; off <<= 1) { __syncthreads(); __syncthreads(); }
    }
    __syncthreads();
    int blockOff = (blockIdx.x > 0) ? sp[blockIdx.x - 1] : 0;

    int idx = blockIdx.x * SCAN_CHUNK + tid;
    int v = (idx < n) ? g_cnt[idx] : 0;
    s[tid] = v;
    __syncthreads();
    for (int off = 1; off < SCAN_CHUNK; off <<= 1) {
        int a = (tid >= off) ? s[tid - off] : 0;
        __syncthreads();
        s[tid] += a;
        __syncthreads();
    }
    if (idx < n) g_ptr[idx] = blockOff + s[tid] - v;
}

// ---------------- 5: build — scatter (src, w); cursor folded into g_ptr ----------------
__global__ void __launch_bounds__(256) k_build(const int* __restrict__ row,
                                               const int* __restrict__ col,
                                               const float* __restrict__ w, int E) {
    long i0 = ((long)blockIdx.x * blockDim.x + threadIdx.x) * 4;
    if (i0 >= E) return;
    if (i0 + 3 < E) {
        int4   r4 = *(const int4*)  (row + i0);
        int4   c4 = *(const int4*)  (col + i0);
        float4 w4 = *(const float4*)(w   + i0);
        int p0 = atomicAdd(&g_ptr[c4.x], 1);
        g_edge[p0] = make_int2(r4.x, __float_as_int(w4.x));
        int p1 = atomicAdd(&g_ptr[c4.y], 1);
        g_edge[p1] = make_int2(r4.y, __float_as_int(w4.y));
        int p2 = atomicAdd(&g_ptr[c4.z], 1);
        g_edge[p2] = make_int2(r4.z, __float_as_int(w4.z));
        int p3 = atomicAdd(&g_ptr[c4.w], 1);
        g_edge[p3] = make_int2(r4.w, __float_as_int(w4.w));
    } else {
        for (long k = i0; k < E; k++) {
            int pos = atomicAdd(&g_ptr[col[k]], 1);
            g_edge[pos] = make_int2(row[k], __float_as_int(w[k]));
        }
    }
}

// ---------------- 6: agg1 ----------------
__global__ void k_agg1(const float* __restrict__ bias, int n) {
    const float4* in = (const float4*)g_hx;
    int node = (blockIdx.x * blockDim.x + threadIdx.x) >> 5;
    int lane = threadIdx.x & 31;
    if (node >= n) return;

    int q  = lane & 3;
    int es = lane >> 2;
    int end   = g_ptr[node];
    int start = end - g_cnt[node];

    float4 acc = make_float4(0.f, 0.f, 0.f, 0.f);
    for (int e = start + es; e < end; e += 8) {
        int2  ev = __ldg(&g_edge[e]);
        float wv = __int_as_float(ev.y);
        float4 v = in[ev.x * 4 + q];
        acc.x += wv * v.x; acc.y += wv * v.y; acc.z += wv * v.z; acc.w += wv * v.w;
    }
    #pragma unroll
    for (int off = 4; off < 32; off <<= 1) {
        acc.x += __shfl_down_sync(0xffffffffu, acc.x, off);
        acc.y += __shfl_down_sync(0xffffffffu, acc.y, off);
        acc.z += __shfl_down_sync(0xffffffffu, acc.z, off);
        acc.w += __shfl_down_sync(0xffffffffu, acc.w, off);
    }
    if (lane < 4) {
        float d = g_dinv[node];
        float4 sv = in[node * 4 + lane];
        float4 b = ((const float4*)bias)[lane];
        acc.x = d * fmaxf(d * (acc.x + sv.x) + b.x, 0.f);
        acc.y = d * fmaxf(d * (acc.y + sv.y) + b.y, 0.f);
        acc.z = d * fmaxf(d * (acc.z + sv.z) + b.z, 0.f);
        acc.w = d * fmaxf(d * (acc.w + sv.w) + b.w, 0.f);
        ((float4*)g_h1)[node * 4 + lane] = acc;
    }
}

// ---------------- 7: agg2 + output GEMM ----------------
__global__ void k_agg2_out(float* __restrict__ out, const float* __restrict__ W2,
                           const float* __restrict__ b2, int n) {
    __shared__ float W2s[HID * NC];
    __shared__ float b2s[NC];
    int tid = threadIdx.x;
    for (int i = tid; i < HID * NC; i += blockDim.x) W2s[i] = W2[i];
    if (tid < NC) b2s[tid] = b2[tid];
    __syncthreads();

    const float4* in = (const float4*)g_h1;
    int node = (blockIdx.x * blockDim.x + tid) >> 5;
    int lane = tid & 31;
    if (node >= n) return;

    int q  = lane & 3;
    int es = lane >> 2;
    int end   = g_ptr[node];
    int start = end - g_cnt[node];

    float4 acc = make_float4(0.f, 0.f, 0.f, 0.f);
    for (int e = start + es; e < end; e += 8) {
        int2  ev = __ldg(&g_edge[e]);
        float wv = __int_as_float(ev.y);
        float4 v = in[ev.x * 4 + q];
        acc.x += wv * v.x; acc.y += wv * v.y; acc.z += wv * v.z; acc.w += wv * v.w;
    }
    #pragma unroll
    for (int off = 4; off < 32; off <<= 1) {
        acc.x += __shfl_down_sync(0xffffffffu, acc.x, off);
        acc.y += __shfl_down_sync(0xffffffffu, acc.y, off);
        acc.z += __shfl_down_sync(0xffffffffu, acc.z, off);
        acc.w += __shfl_down_sync(0xffffffffu, acc.w, off);
    }
    if (lane < 4) {
        float d = g_dinv[node];
        float4 sv = in[node * 4 + lane];
        acc.x = d * (acc.x + sv.x);
        acc.y = d * (acc.y + sv.y);
        acc.z = d * (acc.z + sv.z);
        acc.w = d * (acc.w + sv.w);
    }
    float h[16];
    #pragma unroll
    for (int s = 0; s < 4; s++) {
        h[4 * s + 0] = __shfl_sync(0xffffffffu, acc.x, s);
        h[4 * s + 1] = __shfl_sync(0xffffffffu, acc.y, s);
        h[4 * s + 2] = __shfl_sync(0xffffffffu, acc.z, s);
        h[4 * s + 3] = __shfl_sync(0xffffffffu, acc.w, s);
    }
    if (lane < NC / 2) {
        int c = 2 * lane;
        float s0 = b2s[c], s1 = b2s[c + 1];
        #pragma unroll
        for (int k = 0; k < HID; k++) {
            s0 += h[k] * W2s[k * NC + c];
            s1 += h[k] * W2s[k * NC + c + 1];
        }
        ((float2*)&out[node * NC])[lane] = make_float2(s0, s1);
    }
}

// ---------------- launch ----------------
extern "C" void kernel_launch(void* const* d_in, const int* in_sizes, int n_in,
                              void* d_out, int out_size) {
    const float* x  = (const float*)d_in[0];
    const int*   ei = (const int*)  d_in[1];
    const float* ew = (const float*)d_in[2];
    const float* W1 = (const float*)d_in[3];
    const float* b1 = (const float*)d_in[4];
    const float* W2 = (const float*)d_in[5];
    const float* b2 = (const float*)d_in[6];

    int E = in_sizes[2];
    int n = in_sizes[0] / DF;
    const int* rowp = ei;
    const int* colp = ei + E;

    int nb256 = (n + 255) / 256;
    int eb4   = (int)(((long)E + 1023) / 1024);

    k_init  <<<nb256, 256>>>(n);                          // 0
    k_pass1 <<<eb4, 256>>>(colp, ew, E);                  // 1
    k_scanA <<<NB, 256>>>(n);                             // 2
    k_gemm1 <<<(n + 255) / 256, 256>>>(x, W1, n);         // 3  <- profiled
    k_scanC <<<NB, SCAN_CHUNK>>>(n);                      // 4
    k_build <<<eb4, 256>>>(rowp, colp, ew, E);            // 5
    long wthreads = (long)n * 32;
    int aggblocks = (int)((wthreads + 255) / 256);
    k_agg1     <<<aggblocks, 256>>>(b1, n);               // 6
    k_agg2_out <<<aggblocks, 256>>>((float*)d_out, W2, b2, n); // 7
}

// round 9
// speedup vs baseline: 1.4450x; 1.0234x over previous
#include <cuda_runtime.h>

#define NN 100000
#define NE 3200000
#define DF 512
#define HID 16
#define NC  40
#define SCAN_CHUNK 1024
#define NB ((NN + SCAN_CHUNK - 1) / SCAN_CHUNK)   // 98

typedef unsigned long long ull;

// ---------------- device scratch ----------------
__device__ ull   g_pack[NN];   // (cnt << 40) | fixed20(weighted degree)
__device__ float g_dinv[NN];   // d^-1/2
__device__ int   g_cnt[NN];    // in-degree (edges only)
__device__ int   g_ptr[NN];    // CSR offsets; after build: end offsets
__device__ int2  g_edge[NE];   // (src, w-as-int) per CSR slot
__device__ float g_hx [NN * HID];
__device__ float g_h1 [NN * HID];
__device__ int   g_part[NB];

#define FMA2(d, a, b) asm("fma.rn.f32x2 %0, %1, %2, %0;" : "+l"(d) : "l"(a), "l"(b))
#define MUL2(d, a, b) asm("mul.rn.f32x2 %0, %1, %2;" : "=l"(d) : "l"(a), "l"(b))

// ---------------- 0: init ----------------
__global__ void k_init(int n) {
    int i = blockIdx.x * blockDim.x + threadIdx.x;
    if (i < n) g_pack[i] = (1ULL << 20);   // self-loop w=1.0 in fixed20, cnt=0
}

// ---------------- 1: pass1 — single packed 64-bit atomic per edge ----------------
__global__ void __launch_bounds__(256) k_pass1(const int* __restrict__ col,
                                               const float* __restrict__ w, int E) {
    long i0 = ((long)blockIdx.x * blockDim.x + threadIdx.x) * 4;
    if (i0 >= E) return;
    if (i0 + 3 < E) {
        int4   c4 = *(const int4*)  (col + i0);
        float4 w4 = *(const float4*)(w   + i0);
        atomicAdd(&g_pack[c4.x], (1ULL << 40) + (ull)(w4.x * 1048576.0f + 0.5f));
        atomicAdd(&g_pack[c4.y], (1ULL << 40) + (ull)(w4.y * 1048576.0f + 0.5f));
        atomicAdd(&g_pack[c4.z], (1ULL << 40) + (ull)(w4.z * 1048576.0f + 0.5f));
        atomicAdd(&g_pack[c4.w], (1ULL << 40) + (ull)(w4.w * 1048576.0f + 0.5f));
    } else {
        for (long k = i0; k < E; k++)
            atomicAdd(&g_pack[col[k]], (1ULL << 40) + (ull)(w[k] * 1048576.0f + 0.5f));
    }
}

// ---------------- 2: scanA — unpack, rsqrt, per-chunk sums ----------------
__global__ void k_scanA(int n) {
    __shared__ int sh[256];
    int t = threadIdx.x;
    int base = blockIdx.x * SCAN_CHUNK;
    int s = 0;
    #pragma unroll
    for (int k = 0; k < 4; k++) {
        int idx = base + t + k * 256;
        if (idx < n) {
            ull p = g_pack[idx];
            int cnt = (int)(p >> 40);
            float deg = (float)(p & ((1ULL << 40) - 1)) * (1.0f / 1048576.0f);
            g_cnt[idx]  = cnt;
            g_dinv[idx] = rsqrtf(deg);
            s += cnt;
        }
    }
    sh[t] = s;
    __syncthreads();
    for (int off = 128; off > 0; off >>= 1) {
        if (t < off) sh[t] += sh[t + off];
        __syncthreads();
    }
    if (t == 0) g_part[blockIdx.x] = sh[0];
}

// ---------------- 3: GEMM1 (PROFILED) — g_hx = dinv[row] * (x @ W1) ----------------
// 128 threads = 4 warps; R=2 rows per thread (64 rows/warp, 256 rows/block).
// W in shared (LDS.128 broadcast, amortized over 2 rows); per-warp x slices
// (stride-17, scalar access -> conflict-free & aligned); no block syncs in loop.
// Dynamic smem: [0,32KB) = W packed as ull; [32KB, +4*64*17*4) = x tiles.
__global__ void __launch_bounds__(128) k_gemm1(const float* __restrict__ x,
                                               const float* __restrict__ W1, int n) {
    extern __shared__ char smraw[];
    ull*   Ws = (ull*)smraw;                     // 32 KB: Ws[k*8+p] = W1[k*16+2p..2p+1]
    float* xs = (float*)(smraw + DF * HID * 4);  // 4 warps * 64 rows * 17 floats

    int t = threadIdx.x;
    int w = t >> 5, l = t & 31;
    int lr = l >> 2;                      // sub-row 0..7
    int lc = l & 3;                       // col-quad 0..3
    float* xw = xs + w * (64 * 17);       // this warp's 64x17 tile

    {   // cooperative W load (only block-wide sync in the kernel)
        const ulonglong2* Wg = (const ulonglong2*)W1;
        ulonglong2* Ws2 = (ulonglong2*)Ws;
        #pragma unroll
        for (int i = 0; i < DF * HID / 4 / 128; i++)
            Ws2[i * 128 + t] = Wg[i * 128 + t];
    }
    __syncthreads();

    int rowbase = blockIdx.x * 256 + w * 64;
    int rowA = rowbase + l;
    int rowB = rowbase + 32 + l;

    ull accA[8], accB[8];
    #pragma unroll
    for (int p = 0; p < 8; p++) { accA[p] = 0ULL; accB[p] = 0ULL; }

    // register prefetch of chunk 0: rows rowbase + lr + 8i (i=0..7), cols lc*4..lc*4+3
    float4 r[8];
    {
        const float4 z = make_float4(0.f, 0.f, 0.f, 0.f);
        #pragma unroll
        for (int i = 0; i < 8; i++) {
            int gr = rowbase + lr + 8 * i;
            r[i] = (gr < n) ? ((const float4*)&x[(size_t)gr * DF])[lc] : z;
        }
    }

    for (int jb = 0; jb < DF; jb += 16) {
        __syncwarp();
        #pragma unroll
        for (int i = 0; i < 8; i++) {
            float* dst = xw + (lr + 8 * i) * 17 + lc * 4;
            dst[0] = r[i].x; dst[1] = r[i].y; dst[2] = r[i].z; dst[3] = r[i].w;
        }
        __syncwarp();

        if (jb + 16 < DF) {   // prefetch next chunk while computing this one
            int j2 = jb + 16;
            const float4 z = make_float4(0.f, 0.f, 0.f, 0.f);
            #pragma unroll
            for (int i = 0; i < 8; i++) {
                int gr = rowbase + lr + 8 * i;
                r[i] = (gr < n) ? ((const float4*)&x[(size_t)gr * DF + j2])[lc] : z;
            }
        }

        #pragma unroll
        for (int c = 0; c < 16; c++) {
            float xa = xw[l * 17 + c];          // scalar LDS, conflict-free
            float xb = xw[(32 + l) * 17 + c];
            ull ax, bx;
            asm("mov.b64 %0, {%1, %1};" : "=l"(ax) : "f"(xa));
            asm("mov.b64 %0, {%1, %1};" : "=l"(bx) : "f"(xb));
            const ulonglong2* wp = (const ulonglong2*)&Ws[(jb + c) * 8];
            ulonglong2 w01 = wp[0], w23 = wp[1];
            FMA2(accA[0], ax, w01.x); FMA2(accB[0], bx, w01.x);
            FMA2(accA[1], ax, w01.y); FMA2(accB[1], bx, w01.y);
            FMA2(accA[2], ax, w23.x); FMA2(accB[2], bx, w23.x);
            FMA2(accA[3], ax, w23.y); FMA2(accB[3], bx, w23.y);
            ulonglong2 w45 = wp[2], w67 = wp[3];
            FMA2(accA[4], ax, w45.x); FMA2(accB[4], bx, w45.x);
            FMA2(accA[5], ax, w45.y); FMA2(accB[5], bx, w45.y);
            FMA2(accA[6], ax, w67.x); FMA2(accB[6], bx, w67.x);
            FMA2(accA[7], ax, w67.y); FMA2(accB[7], bx, w67.y);
        }
    }

    if (rowA < n) {
        float d = g_dinv[rowA];
        ull dd;
        asm("mov.b64 %0, {%1, %1};" : "=l"(dd) : "f"(d));
        #pragma unroll
        for (int p = 0; p < 8; p++) MUL2(accA[p], accA[p], dd);
        ulonglong2* o = (ulonglong2*)&g_hx[(size_t)rowA * HID];
        o[0] = make_ulonglong2(accA[0], accA[1]);
        o[1] = make_ulonglong2(accA[2], accA[3]);
        o[2] = make_ulonglong2(accA[4], accA[5]);
        o[3] = make_ulonglong2(accA[6], accA[7]);
    }
    if (rowB < n) {
        float d = g_dinv[rowB];
        ull dd;
        asm("mov.b64 %0, {%1, %1};" : "=l"(dd) : "f"(d));
        #pragma unroll
        for (int p = 0; p < 8; p++) MUL2(accB[p], accB[p], dd);
        ulonglong2* o = (ulonglong2*)&g_hx[(size_t)rowB * HID];
        o[0] = make_ulonglong2(accB[0], accB[1]);
        o[1] = make_ulonglong2(accB[2], accB[3]);
        o[2] = make_ulonglong2(accB[4], accB[5]);
        o[3] = make_ulonglong2(accB[6], accB[7]);
    }
}

#define GEMM_SMEM (DF * HID * 4 + 4 * 64 * 17 * 4)   // 32768 + 17408 = 50176

// ---------------- 4: scanC — local scan of partials + chunk scan -> g_ptr ----------------
__global__ void k_scanC(int n) {
    __shared__ int sp[128];
    __shared__ int s[SCAN_CHUNK];
    int t = threadIdx.x % 128;
    int tid = threadIdx.x;

    if (tid < 128) sp[tid] = (tid < NB) ? g_part[tid] : 0;
    __syncthreads();
    if (tid < 128) {
        #pragma unroll
        for (int off = 1; off < 128; off <<= 1) {
            int a = (t >= off) ? sp[t - off] : 0;
            __syncthreads();
            sp[t] += a;
            __syncthreads();
        }
    } else {
        #pragma unroll
        for (int off = 1; off < 128; off <<= 1) { __syncthreads(); __syncthreads(); }
    }
    __syncthreads();
    int blockOff = (blockIdx.x > 0) ? sp[blockIdx.x - 1] : 0;

    int idx = blockIdx.x * SCAN_CHUNK + tid;
    int v = (idx < n) ? g_cnt[idx] : 0;
    s[tid] = v;
    __syncthreads();
    for (int off = 1; off < SCAN_CHUNK; off <<= 1) {
        int a = (tid >= off) ? s[tid - off] : 0;
        __syncthreads();
        s[tid] += a;
        __syncthreads();
    }
    if (idx < n) g_ptr[idx] = blockOff + s[tid] - v;
}

// ---------------- 5: build — scatter (src, w); cursor folded into g_ptr ----------------
__global__ void __launch_bounds__(256) k_build(const int* __restrict__ row,
                                               const int* __restrict__ col,
                                               const float* __restrict__ w, int E) {
    long i0 = ((long)blockIdx.x * blockDim.x + threadIdx.x) * 4;
    if (i0 >= E) return;
    if (i0 + 3 < E) {
        int4   r4 = *(const int4*)  (row + i0);
        int4   c4 = *(const int4*)  (col + i0);
        float4 w4 = *(const float4*)(w   + i0);
        int p0 = atomicAdd(&g_ptr[c4.x], 1);
        g_edge[p0] = make_int2(r4.x, __float_as_int(w4.x));
        int p1 = atomicAdd(&g_ptr[c4.y], 1);
        g_edge[p1] = make_int2(r4.y, __float_as_int(w4.y));
        int p2 = atomicAdd(&g_ptr[c4.z], 1);
        g_edge[p2] = make_int2(r4.z, __float_as_int(w4.z));
        int p3 = atomicAdd(&g_ptr[c4.w], 1);
        g_edge[p3] = make_int2(r4.w, __float_as_int(w4.w));
    } else {
        for (long k = i0; k < E; k++) {
            int pos = atomicAdd(&g_ptr[col[k]], 1);
            g_edge[pos] = make_int2(row[k], __float_as_int(w[k]));
        }
    }
}

// ---------------- 6: agg1 ----------------
__global__ void k_agg1(const float* __restrict__ bias, int n) {
    const float4* in = (const float4*)g_hx;
    int node = (blockIdx.x * blockDim.x + threadIdx.x) >> 5;
    int lane = threadIdx.x & 31;
    if (node >= n) return;

    int q  = lane & 3;
    int es = lane >> 2;
    int end   = g_ptr[node];
    int start = end - g_cnt[node];

    float4 acc = make_float4(0.f, 0.f, 0.f, 0.f);
    for (int e = start + es; e < end; e += 8) {
        int2  ev = __ldg(&g_edge[e]);
        float wv = __int_as_float(ev.y);
        float4 v = in[ev.x * 4 + q];
        acc.x += wv * v.x; acc.y += wv * v.y; acc.z += wv * v.z; acc.w += wv * v.w;
    }
    #pragma unroll
    for (int off = 4; off < 32; off <<= 1) {
        acc.x += __shfl_down_sync(0xffffffffu, acc.x, off);
        acc.y += __shfl_down_sync(0xffffffffu, acc.y, off);
        acc.z += __shfl_down_sync(0xffffffffu, acc.z, off);
        acc.w += __shfl_down_sync(0xffffffffu, acc.w, off);
    }
    if (lane < 4) {
        float d = g_dinv[node];
        float4 sv = in[node * 4 + lane];
        float4 b = ((const float4*)bias)[lane];
        acc.x = d * fmaxf(d * (acc.x + sv.x) + b.x, 0.f);
        acc.y = d * fmaxf(d * (acc.y + sv.y) + b.y, 0.f);
        acc.z = d * fmaxf(d * (acc.z + sv.z) + b.z, 0.f);
        acc.w = d * fmaxf(d * (acc.w + sv.w) + b.w, 0.f);
        ((float4*)g_h1)[node * 4 + lane] = acc;
    }
}

// ---------------- 7: agg2 + output GEMM ----------------
__global__ void k_agg2_out(float* __restrict__ out, const float* __restrict__ W2,
                           const float* __restrict__ b2, int n) {
    __shared__ float W2s[HID * NC];
    __shared__ float b2s[NC];
    int tid = threadIdx.x;
    for (int i = tid; i < HID * NC; i += blockDim.x) W2s[i] = W2[i];
    if (tid < NC) b2s[tid] = b2[tid];
    __syncthreads();

    const float4* in = (const float4*)g_h1;
    int node = (blockIdx.x * blockDim.x + tid) >> 5;
    int lane = tid & 31;
    if (node >= n) return;

    int q  = lane & 3;
    int es = lane >> 2;
    int end   = g_ptr[node];
    int start = end - g_cnt[node];

    float4 acc = make_float4(0.f, 0.f, 0.f, 0.f);
    for (int e = start + es; e < end; e += 8) {
        int2  ev = __ldg(&g_edge[e]);
        float wv = __int_as_float(ev.y);
        float4 v = in[ev.x * 4 + q];
        acc.x += wv * v.x; acc.y += wv * v.y; acc.z += wv * v.z; acc.w += wv * v.w;
    }
    #pragma unroll
    for (int off = 4; off < 32; off <<= 1) {
        acc.x += __shfl_down_sync(0xffffffffu, acc.x, off);
        acc.y += __shfl_down_sync(0xffffffffu, acc.y, off);
        acc.z += __shfl_down_sync(0xffffffffu, acc.z, off);
        acc.w += __shfl_down_sync(0xffffffffu, acc.w, off);
    }
    if (lane < 4) {
        float d = g_dinv[node];
        float4 sv = in[node * 4 + lane];
        acc.x = d * (acc.x + sv.x);
        acc.y = d * (acc.y + sv.y);
        acc.z = d * (acc.z + sv.z);
        acc.w = d * (acc.w + sv.w);
    }
    float h[16];
    #pragma unroll
    for (int s = 0; s < 4; s++) {
        h[4 * s + 0] = __shfl_sync(0xffffffffu, acc.x, s);
        h[4 * s + 1] = __shfl_sync(0xffffffffu, acc.y, s);
        h[4 * s + 2] = __shfl_sync(0xffffffffu, acc.z, s);
        h[4 * s + 3] = __shfl_sync(0xffffffffu, acc.w, s);
    }
    if (lane < NC / 2) {
        int c = 2 * lane;
        float s0 = b2s[c], s1 = b2s[c + 1];
        #pragma unroll
        for (int k = 0; k < HID; k++) {
            s0 += h[k] * W2s[k * NC + c];
            s1 += h[k] * W2s[k * NC + c + 1];
        }
        ((float2*)&out[node * NC])[lane] = make_float2(s0, s1);
    }
}

// ---------------- launch ----------------
extern "C" void kernel_launch(void* const* d_in, const int* in_sizes, int n_in,
                              void* d_out, int out_size) {
    const float* x  = (const float*)d_in[0];
    const int*   ei = (const int*)  d_in[1];
    const float* ew = (const float*)d_in[2];
    const float* W1 = (const float*)d_in[3];
    const float* b1 = (const float*)d_in[4];
    const float* W2 = (const float*)d_in[5];
    const float* b2 = (const float*)d_in[6];

    int E = in_sizes[2];
    int n = in_sizes[0] / DF;
    const int* rowp = ei;
    const int* colp = ei + E;

    int nb256 = (n + 255) / 256;
    int eb4   = (int)(((long)E + 1023) / 1024);

    static int smem_set = 0;
    if (!smem_set) {
        cudaFuncSetAttribute(k_gemm1, cudaFuncAttributeMaxDynamicSharedMemorySize, GEMM_SMEM);
        smem_set = 1;
    }

    k_init  <<<nb256, 256>>>(n);                          // 0
    k_pass1 <<<eb4, 256>>>(colp, ew, E);                  // 1
    k_scanA <<<NB, 256>>>(n);                             // 2
    k_gemm1 <<<(n + 255) / 256, 128, GEMM_SMEM>>>(x, W1, n); // 3  <- profiled
    k_scanC <<<NB, SCAN_CHUNK>>>(n);                      // 4
    k_build <<<eb4, 256>>>(rowp, colp, ew, E);            // 5
    long wthreads = (long)n * 32;
    int aggblocks = (int)((wthreads + 255) / 256);
    k_agg1     <<<aggblocks, 256>>>(b1, n);               // 6
    k_agg2_out <<<aggblocks, 256>>>((float*)d_out, W2, b2, n); // 7
}